// round 2
// baseline (speedup 1.0000x reference)
#include <cuda_runtime.h>
#include <cuda_bf16.h>
#include <cstdint>
#include <cstddef>

#define DEV __device__ __forceinline__

// ---------------------------------------------------------------------------
// Problem constants (B, L, D, FF fixed by the reference)
// ---------------------------------------------------------------------------
constexpr int Bb  = 4;
constexpr int Ll  = 4096;
constexpr int Dd  = 1024;
constexpr int FFd = 2048;
constexpr int ROWS = Bb * Ll;                       // 16384 rows
constexpr size_t BLD = (size_t)ROWS * Dd;           // 16,777,216
constexpr size_t BLF = (size_t)ROWS * FFd;          // 33,554,432
constexpr int CH = 64;                              // conv chunk length
constexpr int NC = Ll / CH;                         // 64 chunks per sequence
constexpr float EPSF = 1e-5f;

// ---------------------------------------------------------------------------
// Scratch (device globals: allocation-guard-safe)
// ---------------------------------------------------------------------------
__device__ float          g_xn[BLD];                // LN1 output (fp32, conv input)
__device__ __nv_bfloat16  g_xhi[BLD], g_xlo[BLD];   // split of original x (fc GEMM A)
__device__ float          g_conv[BLD];              // spiral conv output
__device__ float          g_x2[BLD];                // conv*y + x
__device__ __nv_bfloat16  g_x3hi[BLD], g_x3lo[BLD]; // split of LN2 output (GEMM1 A)
__device__ __nv_bfloat16  g_uhi[BLF], g_ulo[BLF];   // split of silu(x3@w1+b1) (GEMM2 A)
__device__ float2         g_carry[Bb * NC * Dd];    // conv chunk-local end states
__device__ float2         g_win[Bb * NC * Dd];      // conv chunk entry states
__device__ __nv_bfloat16  g_fcwhi[Dd * Dd],  g_fcwlo[Dd * Dd];
__device__ __nv_bfloat16  g_w1hi[Dd * FFd],  g_w1lo[Dd * FFd];
__device__ __nv_bfloat16  g_w2hi[FFd * Dd],  g_w2lo[FFd * Dd];

// ---------------------------------------------------------------------------
// Small helpers
// ---------------------------------------------------------------------------
DEV uint32_t smem_u32(const void* p) {
    return (uint32_t)__cvta_generic_to_shared(p);
}

DEV void cp16(void* s, const void* g) {
    asm volatile("cp.async.cg.shared.global [%0], [%1], 16;\n"
                 :: "r"(smem_u32(s)), "l"(g));
}
DEV void cp_commit() { asm volatile("cp.async.commit_group;\n"); }
template <int NN> DEV void cp_wait() {
    asm volatile("cp.async.wait_group %0;\n" :: "n"(NN));
}

DEV void ldm_x4(uint32_t* r, uint32_t addr) {
    asm volatile("ldmatrix.sync.aligned.m8n8.x4.shared.b16 {%0,%1,%2,%3}, [%4];"
                 : "=r"(r[0]), "=r"(r[1]), "=r"(r[2]), "=r"(r[3]) : "r"(addr));
}

DEV void ldm_x2t(uint32_t* r, uint32_t addr) {
    asm volatile("ldmatrix.sync.aligned.m8n8.x2.trans.shared.b16 {%0,%1}, [%2];"
                 : "=r"(r[0]), "=r"(r[1]) : "r"(addr));
}

DEV void mma_bf16(float* c, const uint32_t* a, const uint32_t* b) {
    asm volatile(
        "mma.sync.aligned.m16n8k16.row.col.f32.bf16.bf16.f32 "
        "{%0,%1,%2,%3}, {%4,%5,%6,%7}, {%8,%9}, {%0,%1,%2,%3};"
        : "+f"(c[0]), "+f"(c[1]), "+f"(c[2]), "+f"(c[3])
        : "r"(a[0]), "r"(a[1]), "r"(a[2]), "r"(a[3]), "r"(b[0]), "r"(b[1]));
}

DEV float silu(float v) { return v / (1.0f + expf(-v)); }

DEV void split4(float4 v, __nv_bfloat16* hi, __nv_bfloat16* lo) {
    __nv_bfloat16 h0 = __float2bfloat16(v.x);
    __nv_bfloat16 h1 = __float2bfloat16(v.y);
    __nv_bfloat16 h2 = __float2bfloat16(v.z);
    __nv_bfloat16 h3 = __float2bfloat16(v.w);
    *reinterpret_cast<__nv_bfloat162*>(hi)     = __halves2bfloat162(h0, h1);
    *reinterpret_cast<__nv_bfloat162*>(hi + 2) = __halves2bfloat162(h2, h3);
    __nv_bfloat16 l0 = __float2bfloat16(v.x - __bfloat162float(h0));
    __nv_bfloat16 l1 = __float2bfloat16(v.y - __bfloat162float(h1));
    __nv_bfloat16 l2 = __float2bfloat16(v.z - __bfloat162float(h2));
    __nv_bfloat16 l3 = __float2bfloat16(v.w - __bfloat162float(h3));
    *reinterpret_cast<__nv_bfloat162*>(lo)     = __halves2bfloat162(l0, l1);
    *reinterpret_cast<__nv_bfloat162*>(lo + 2) = __halves2bfloat162(l2, l3);
}

// ---------------------------------------------------------------------------
// Weight split: fp32 -> bf16 hi + bf16 lo (once per launch; tiny)
// ---------------------------------------------------------------------------
__global__ void split_weights_kernel(const float* __restrict__ fcw,
                                     const float* __restrict__ w1,
                                     const float* __restrict__ w2) {
    int i = blockIdx.x * blockDim.x + threadIdx.x;
    if (i < Dd * Dd) {
        float v = fcw[i];
        __nv_bfloat16 h = __float2bfloat16(v);
        g_fcwhi[i] = h;
        g_fcwlo[i] = __float2bfloat16(v - __bfloat162float(h));
    }
    if (i < Dd * FFd) {
        float v = w1[i];
        __nv_bfloat16 h = __float2bfloat16(v);
        g_w1hi[i] = h;
        g_w1lo[i] = __float2bfloat16(v - __bfloat162float(h));
    }
    if (i < FFd * Dd) {
        float v = w2[i];
        __nv_bfloat16 h = __float2bfloat16(v);
        g_w2hi[i] = h;
        g_w2lo[i] = __float2bfloat16(v - __bfloat162float(h));
    }
}

// ---------------------------------------------------------------------------
// LayerNorm. STAGE 0: in = x (param). Writes g_xn (fp32 normed) + hi/lo split
//                    of the ORIGINAL x (fc GEMM input).
// STAGE 1: in = g_x2 (global).  Writes hi/lo split of the NORMED value (x3).
// One block (256 threads) per row of 1024.
// ---------------------------------------------------------------------------
template <int STAGE>
__global__ void __launch_bounds__(256) ln_kernel(const float* __restrict__ xin,
                                                 const float* __restrict__ gamma,
                                                 const float* __restrict__ beta) {
    __shared__ float s_part[8], q_part[8], s_stats[2];
    const int row = blockIdx.x;
    const int tid = threadIdx.x;
    const float* src = (STAGE == 0) ? xin : g_x2;
    const float4 v = reinterpret_cast<const float4*>(src + (size_t)row * Dd)[tid];

    float s = v.x + v.y + v.z + v.w;
    float q = v.x * v.x + v.y * v.y + v.z * v.z + v.w * v.w;
#pragma unroll
    for (int o = 16; o > 0; o >>= 1) {
        s += __shfl_xor_sync(0xffffffffu, s, o);
        q += __shfl_xor_sync(0xffffffffu, q, o);
    }
    const int warp = tid >> 5, lane = tid & 31;
    if (lane == 0) { s_part[warp] = s; q_part[warp] = q; }
    __syncthreads();
    if (warp == 0) {
        float ss = (lane < 8) ? s_part[lane] : 0.0f;
        float qq = (lane < 8) ? q_part[lane] : 0.0f;
#pragma unroll
        for (int o = 4; o > 0; o >>= 1) {
            ss += __shfl_xor_sync(0xffffffffu, ss, o);
            qq += __shfl_xor_sync(0xffffffffu, qq, o);
        }
        if (lane == 0) {
            float m = ss * (1.0f / Dd);
            float var = qq * (1.0f / Dd) - m * m;
            s_stats[0] = m;
            s_stats[1] = rsqrtf(var + EPSF);
        }
    }
    __syncthreads();
    const float m = s_stats[0], r = s_stats[1];

    const float4 gg = reinterpret_cast<const float4*>(gamma)[tid];
    const float4 bb = reinterpret_cast<const float4*>(beta)[tid];
    float4 n;
    n.x = (v.x - m) * r * gg.x + bb.x;
    n.y = (v.y - m) * r * gg.y + bb.y;
    n.z = (v.z - m) * r * gg.z + bb.z;
    n.w = (v.w - m) * r * gg.w + bb.w;

    const size_t base = (size_t)row * Dd + (size_t)tid * 4;
    if (STAGE == 0) {
        *reinterpret_cast<float4*>(&g_xn[base]) = n;
        split4(v, &g_xhi[base], &g_xlo[base]);   // split ORIGINAL x
    } else {
        split4(n, &g_x3hi[base], &g_x3lo[base]); // split normed x3
    }
}

// ---------------------------------------------------------------------------
// Spiral conv = single-pole complex IIR:
//   W[-1] = lci;  W[t] = phz*W[t-1] + phi*xn[t];  conv[t] = Re(W[t])
// 3-phase chunked scan, chunk length CH along L, one thread per (b, d, chunk).
// ---------------------------------------------------------------------------
template <bool WRITE>
__global__ void __launch_bounds__(256) conv_chunk_kernel(const float* __restrict__ ph_re,
                                                         const float* __restrict__ ph_im,
                                                         const float* __restrict__ phi_re,
                                                         const float* __restrict__ phi_im) {
    const int d = blockIdx.x * blockDim.x + threadIdx.x;  // 0..1023
    const int c = blockIdx.y;                             // chunk
    const int b = blockIdx.z;                             // batch
    const float pr = ph_re[d], pi = ph_im[d];
    const float a = sqrtf(pr * pr + pi * pi);
    const float sc = expf(-a) / a;
    const float zr = pr * sc, zi = pi * sc;               // phz
    const float fr = phi_re[d], fi = phi_im[d];           // phi

    float Wr, Wi;
    if (WRITE) {
        const float2 w = g_win[(b * NC + c) * Dd + d];
        Wr = w.x; Wi = w.y;
    } else {
        Wr = 0.0f; Wi = 0.0f;
    }
    const size_t base = ((size_t)(b * Ll + c * CH)) * Dd + d;
#pragma unroll 4
    for (int j = 0; j < CH; j++) {
        const float xv = g_xn[base + (size_t)j * Dd];
        const float nr = fmaf(zr, Wr, fmaf(-zi, Wi, fr * xv));
        const float ni = fmaf(zr, Wi, fmaf(zi, Wr, fi * xv));
        Wr = nr; Wi = ni;
        if (WRITE) g_conv[base + (size_t)j * Dd] = Wr;
    }
    if (!WRITE) g_carry[(b * NC + c) * Dd + d] = make_float2(Wr, Wi);
}

// Per-channel carry scan across NC chunks (4096 threads total; trivial).
__global__ void __launch_bounds__(256) conv_scan_kernel(const float* __restrict__ ph_re,
                                                        const float* __restrict__ ph_im,
                                                        const float* __restrict__ lci_re,
                                                        const float* __restrict__ lci_im) {
    const int idx = blockIdx.x * blockDim.x + threadIdx.x;  // 0..B*D-1
    const int b = idx >> 10;
    const int d = idx & 1023;
    const float pr = ph_re[d], pi = ph_im[d];
    const float a = sqrtf(pr * pr + pi * pi);
    const float sc = expf(-a) / a;
    float cr = pr * sc, ci = pi * sc;                       // phz
    // phz^CH via repeated squaring (CH = 64 = 2^6)
#pragma unroll
    for (int i = 0; i < 6; i++) {
        const float nr = cr * cr - ci * ci;
        const float ni = 2.0f * cr * ci;
        cr = nr; ci = ni;
    }
    float Wr = lci_re[d], Wi = lci_im[d];                   // W[-1]
    for (int c = 0; c < NC; c++) {
        g_win[(b * NC + c) * Dd + d] = make_float2(Wr, Wi);
        const float2 e = g_carry[(b * NC + c) * Dd + d];
        const float nr = cr * Wr - ci * Wi + e.x;
        const float ni = cr * Wi + ci * Wr + e.y;
        Wr = nr; Wi = ni;
    }
}

// ---------------------------------------------------------------------------
// GEMM, bf16 hi/lo split (3 mma passes: ah*bh + ah*bl + al*bh), fp32 accum.
// Tile 128x128x32, 256 threads = 8 warps (2 x 4), each warp 64x32.
// 2-stage cp.async double-buffered pipeline; dynamic smem 2 x 37,888 B.
// EPI 0: x2 = conv * silu(acc + fc_b) + x      (A = x split,  B = fc_w split)
// EPI 1: u  = silu(acc + b1) -> hi/lo split    (A = x3 split, B = w1 split)
// EPI 2: out = acc + b2 + x2                    (A = u split,  B = w2 split)
// ---------------------------------------------------------------------------
constexpr int BM = 128, BN = 128, BK = 32;
constexpr int LDA = BK + 8;   // 40 elems  (80 B rows; conflict-free ldmatrix)
constexpr int LDB = BN + 8;   // 136 elems (272 B rows)
constexpr int SA_ELEMS = BM * LDA;          // 5120 bf16 = 10240 B
constexpr int SB_ELEMS = BK * LDB;          // 4352 bf16 = 8704 B
constexpr int STAGE_ELEMS = 2 * SA_ELEMS + 2 * SB_ELEMS;  // 18944 bf16 = 37888 B
constexpr int GEMM_SMEM_BYTES = 2 * STAGE_ELEMS * 2;      // 75776 B

template <int EPI, int N, int K>
__global__ void __launch_bounds__(256) gemm_kernel(const float* __restrict__ bias,
                                                   const float* __restrict__ extra,
                                                   float* __restrict__ outp) {
    extern __shared__ __nv_bfloat16 smem[];

    const __nv_bfloat16 *Ah, *Al, *Bh, *Bl;
    if constexpr (EPI == 0) { Ah = g_xhi;  Al = g_xlo;  Bh = g_fcwhi; Bl = g_fcwlo; }
    else if constexpr (EPI == 1) { Ah = g_x3hi; Al = g_x3lo; Bh = g_w1hi; Bl = g_w1lo; }
    else { Ah = g_uhi;  Al = g_ulo;  Bh = g_w2hi; Bl = g_w2lo; }

    const int tid = threadIdx.x;
    const int lane = tid & 31, warp = tid >> 5;
    const int wm = warp & 1, wn = warp >> 1;
    const int bn0 = blockIdx.x * BN;
    const int bm0 = blockIdx.y * BM;

    // per-thread load coordinates (same every K-tile)
    const int ar = tid >> 2, ac = (tid & 3) * 8;             // +128 rows on 2nd step
    const int br = tid >> 4, bc = (tid & 15) * 8;            // +16 rows on 2nd step

    auto load_tile = [&](int stage, int kb) {
        __nv_bfloat16* sAh = smem + stage * STAGE_ELEMS;
        __nv_bfloat16* sAl = sAh + SA_ELEMS;
        __nv_bfloat16* sBh = sAl + SA_ELEMS;
        __nv_bfloat16* sBl = sBh + SB_ELEMS;
#pragma unroll
        for (int i = 0; i < 2; i++) {
            const int arr = ar + i * 64;
            const size_t aoff = (size_t)(bm0 + arr) * K + kb + ac;
            cp16(&sAh[arr * LDA + ac], &Ah[aoff]);
            cp16(&sAl[arr * LDA + ac], &Al[aoff]);
            const int brr = br + i * 16;
            const size_t boff = (size_t)(kb + brr) * N + bn0 + bc;
            cp16(&sBh[brr * LDB + bc], &Bh[boff]);
            cp16(&sBl[brr * LDB + bc], &Bl[boff]);
        }
        cp_commit();
    };

    float acc[4][4][4];
#pragma unroll
    for (int mi = 0; mi < 4; mi++)
#pragma unroll
        for (int ni = 0; ni < 4; ni++)
#pragma unroll
            for (int e = 0; e < 4; e++) acc[mi][ni][e] = 0.0f;

    load_tile(0, 0);

    int cur = 0;
    for (int kb = 0; kb < K; kb += BK) {
        if (kb + BK < K) {
            load_tile(cur ^ 1, kb + BK);
            cp_wait<1>();
        } else {
            cp_wait<0>();
        }
        __syncthreads();

        const __nv_bfloat16* sAh = smem + cur * STAGE_ELEMS;
        const __nv_bfloat16* sAl = sAh + SA_ELEMS;
        const __nv_bfloat16* sBh = sAl + SA_ELEMS;
        const __nv_bfloat16* sBl = sBh + SB_ELEMS;

#pragma unroll
        for (int ks = 0; ks < BK; ks += 16) {
            uint32_t ah[4][4], al[4][4], bh[4][2], bl[4][2];
#pragma unroll
            for (int mi = 0; mi < 4; mi++) {
                const int row = wm * 64 + mi * 16 + (lane & 15);
                const int off = row * LDA + ks + ((lane >> 4) << 3);
                ldm_x4(ah[mi], smem_u32(&sAh[off]));
                ldm_x4(al[mi], smem_u32(&sAl[off]));
            }
#pragma unroll
            for (int ni = 0; ni < 4; ni++) {
                const int off = (ks + (lane & 15)) * LDB + wn * 32 + ni * 8;
                ldm_x2t(bh[ni], smem_u32(&sBh[off]));
                ldm_x2t(bl[ni], smem_u32(&sBl[off]));
            }
#pragma unroll
            for (int mi = 0; mi < 4; mi++)
#pragma unroll
                for (int ni = 0; ni < 4; ni++) {
                    mma_bf16(acc[mi][ni], ah[mi], bh[ni]);
                    mma_bf16(acc[mi][ni], ah[mi], bl[ni]);
                    mma_bf16(acc[mi][ni], al[mi], bh[ni]);
                }
        }
        __syncthreads();   // cur becomes writable for the next prefetch
        cur ^= 1;
    }

    // ---- epilogue ----
#pragma unroll
    for (int mi = 0; mi < 4; mi++) {
#pragma unroll
        for (int ni = 0; ni < 4; ni++) {
            const int col = bn0 + wn * 32 + ni * 8 + (lane & 3) * 2;
            const float b0 = bias[col], b1 = bias[col + 1];
#pragma unroll
            for (int h = 0; h < 2; h++) {
                const int row = bm0 + wm * 64 + mi * 16 + (lane >> 2) + h * 8;
                const size_t idx = (size_t)row * N + col;
                const float v0 = acc[mi][ni][h * 2 + 0] + b0;
                const float v1 = acc[mi][ni][h * 2 + 1] + b1;
                if constexpr (EPI == 0) {
                    const float y0 = silu(v0), y1 = silu(v1);
                    const float2 cv = *reinterpret_cast<const float2*>(&g_conv[idx]);
                    const float2 xv = *reinterpret_cast<const float2*>(&extra[idx]);
                    float2 r;
                    r.x = cv.x * y0 + xv.x;
                    r.y = cv.y * y1 + xv.y;
                    *reinterpret_cast<float2*>(&g_x2[idx]) = r;
                } else if constexpr (EPI == 1) {
                    const float y0 = silu(v0), y1 = silu(v1);
                    const __nv_bfloat16 h0 = __float2bfloat16(y0);
                    const __nv_bfloat16 h1 = __float2bfloat16(y1);
                    const __nv_bfloat16 l0 = __float2bfloat16(y0 - __bfloat162float(h0));
                    const __nv_bfloat16 l1 = __float2bfloat16(y1 - __bfloat162float(h1));
                    *reinterpret_cast<__nv_bfloat162*>(&g_uhi[idx]) = __halves2bfloat162(h0, h1);
                    *reinterpret_cast<__nv_bfloat162*>(&g_ulo[idx]) = __halves2bfloat162(l0, l1);
                } else {
                    const float2 xv = *reinterpret_cast<const float2*>(&g_x2[idx]);
                    float2 r;
                    r.x = v0 + xv.x;
                    r.y = v1 + xv.y;
                    *reinterpret_cast<float2*>(&outp[idx]) = r;
                }
            }
        }
    }
}

// ---------------------------------------------------------------------------
// Launch
// ---------------------------------------------------------------------------
extern "C" void kernel_launch(void* const* d_in, const int* in_sizes, int n_in,
                              void* d_out, int out_size) {
    (void)in_sizes; (void)n_in; (void)out_size;
    const float* x      = (const float*)d_in[0];
    const float* ln_g   = (const float*)d_in[1];
    const float* ln_b   = (const float*)d_in[2];
    const float* fc_w   = (const float*)d_in[3];
    const float* fc_b   = (const float*)d_in[4];
    const float* w1     = (const float*)d_in[5];
    const float* b1     = (const float*)d_in[6];
    const float* w2     = (const float*)d_in[7];
    const float* b2     = (const float*)d_in[8];
    const float* ph_re  = (const float*)d_in[9];
    const float* ph_im  = (const float*)d_in[10];
    const float* phi_re = (const float*)d_in[11];
    const float* phi_im = (const float*)d_in[12];
    const float* lci_re = (const float*)d_in[13];
    const float* lci_im = (const float*)d_in[14];
    float* out = (float*)d_out;

    // Opt in to >48KB dynamic smem (host-side attribute, capture-safe).
    static bool attr_done = false;
    if (!attr_done) {
        cudaFuncSetAttribute(gemm_kernel<0, Dd, Dd>,
                             cudaFuncAttributeMaxDynamicSharedMemorySize, GEMM_SMEM_BYTES);
        cudaFuncSetAttribute(gemm_kernel<1, FFd, Dd>,
                             cudaFuncAttributeMaxDynamicSharedMemorySize, GEMM_SMEM_BYTES);
        cudaFuncSetAttribute(gemm_kernel<2, Dd, FFd>,
                             cudaFuncAttributeMaxDynamicSharedMemorySize, GEMM_SMEM_BYTES);
        attr_done = true;
    }

    // 1) split weights to bf16 hi/lo
    split_weights_kernel<<<(Dd * FFd + 255) / 256, 256>>>(fc_w, w1, w2);

    // 2) LN1: xn = LN(x); also split original x for the fc GEMM
    ln_kernel<0><<<ROWS, 256>>>(x, ln_g, ln_b);

    // 3) spiral conv: chunk-local scan -> carry scan -> replay with outputs
    conv_chunk_kernel<false><<<dim3(Dd / 256, NC, Bb), 256>>>(ph_re, ph_im, phi_re, phi_im);
    conv_scan_kernel<<<(Bb * Dd) / 256, 256>>>(ph_re, ph_im, lci_re, lci_im);
    conv_chunk_kernel<true><<<dim3(Dd / 256, NC, Bb), 256>>>(ph_re, ph_im, phi_re, phi_im);

    // 4) fc GEMM + fused gate/residual epilogue: x2 = conv*silu(x@fc_w+fc_b) + x
    gemm_kernel<0, Dd, Dd><<<dim3(Dd / 128, ROWS / 128), 256, GEMM_SMEM_BYTES>>>(fc_b, x, nullptr);

    // 5) LN2: x3 = LN(x2), split to bf16 hi/lo
    ln_kernel<1><<<ROWS, 256>>>(nullptr, ln_g, ln_b);

    // 6) MLP GEMM 1: u = silu(x3@w1 + b1), split
    gemm_kernel<1, FFd, Dd><<<dim3(FFd / 128, ROWS / 128), 256, GEMM_SMEM_BYTES>>>(b1, nullptr, nullptr);

    // 7) MLP GEMM 2 + final residual: out = x2 + u@w2 + b2
    gemm_kernel<2, Dd, FFd><<<dim3(Dd / 128, ROWS / 128), 256, GEMM_SMEM_BYTES>>>(b2, nullptr, out);
}

// round 6
// speedup vs baseline: 1.9060x; 1.9060x over previous
#include <cuda_runtime.h>
#include <cuda_fp16.h>
#include <cstdint>
#include <cstddef>

#define DEV __device__ __forceinline__

// ---------------------------------------------------------------------------
// Problem constants
// ---------------------------------------------------------------------------
constexpr int Bb  = 4;
constexpr int Ll  = 4096;
constexpr int Dd  = 1024;
constexpr int FFd = 2048;
constexpr int ROWS = Bb * Ll;                       // 16384
constexpr size_t BLD = (size_t)ROWS * Dd;
constexpr size_t BLF = (size_t)ROWS * FFd;
constexpr int CH = 64;
constexpr int NC = Ll / CH;                         // 64
constexpr float EPSF = 1e-5f;

// ---------------------------------------------------------------------------
// Scratch (device globals)
// ---------------------------------------------------------------------------
__device__ float   g_xn[BLD];          // LN1 output (conv input, fp32)
__device__ __half  g_xh[BLD];          // fp16 of original x   (A of fc GEMM)
__device__ float   g_conv[BLD];        // conv output
__device__ float   g_x2[BLD];          // conv*y + x
__device__ __half  g_x3h[BLD];         // fp16 of LN2 output   (A of w1 GEMM)
__device__ __half  g_u[BLF];           // fp16 silu(x3@w1+b1)  (A of w2 GEMM)
__device__ float2  g_carry[Bb * NC * Dd];
__device__ float2  g_win[Bb * NC * Dd];
__device__ __half  g_fcw[Dd * Dd];     // fp16 weights, original [K,N] layout
__device__ __half  g_w1[Dd * FFd];
__device__ __half  g_w2[FFd * Dd];

// ---------------------------------------------------------------------------
// PTX helpers (sm_80-level only: cp.async, ldmatrix, mma.sync)
// ---------------------------------------------------------------------------
DEV uint32_t smem_u32(const void* p) { return (uint32_t)__cvta_generic_to_shared(p); }

DEV void cp16(uint32_t s, const void* g) {
    asm volatile("cp.async.cg.shared.global [%0], [%1], 16;\n" :: "r"(s), "l"(g));
}
DEV void cp_commit() { asm volatile("cp.async.commit_group;\n"); }
template <int NN> DEV void cp_wait() { asm volatile("cp.async.wait_group %0;\n" :: "n"(NN)); }

DEV void ldm_x4(uint32_t* r, uint32_t addr) {
    asm volatile("ldmatrix.sync.aligned.m8n8.x4.shared.b16 {%0,%1,%2,%3}, [%4];"
                 : "=r"(r[0]), "=r"(r[1]), "=r"(r[2]), "=r"(r[3]) : "r"(addr));
}
DEV void ldm_x2t(uint32_t* r, uint32_t addr) {
    asm volatile("ldmatrix.sync.aligned.m8n8.x2.trans.shared.b16 {%0,%1}, [%2];"
                 : "=r"(r[0]), "=r"(r[1]) : "r"(addr));
}
DEV void mma_f16(float* c, const uint32_t* a, const uint32_t* b) {
    asm volatile(
        "mma.sync.aligned.m16n8k16.row.col.f32.f16.f16.f32 "
        "{%0,%1,%2,%3}, {%4,%5,%6,%7}, {%8,%9}, {%0,%1,%2,%3};"
        : "+f"(c[0]), "+f"(c[1]), "+f"(c[2]), "+f"(c[3])
        : "r"(a[0]), "r"(a[1]), "r"(a[2]), "r"(a[3]), "r"(b[0]), "r"(b[1]));
}

DEV float silu(float v) { return v / (1.0f + expf(-v)); }

DEV void toh4(float4 v, __half* dst) {
    *reinterpret_cast<__half2*>(dst)     = __floats2half2_rn(v.x, v.y);
    *reinterpret_cast<__half2*>(dst + 2) = __floats2half2_rn(v.z, v.w);
}

// ---------------------------------------------------------------------------
// Weight convert: fp32 -> fp16 (original [K,N] layout kept)
// ---------------------------------------------------------------------------
__global__ void wconv_kernel(const float* __restrict__ fcw,
                             const float* __restrict__ w1,
                             const float* __restrict__ w2) {
    int i = blockIdx.x * blockDim.x + threadIdx.x;
    if (i < Dd * Dd)  g_fcw[i] = __float2half_rn(fcw[i]);
    if (i < Dd * FFd) g_w1[i]  = __float2half_rn(w1[i]);
    if (i < FFd * Dd) g_w2[i]  = __float2half_rn(w2[i]);
}

// ---------------------------------------------------------------------------
// LayerNorm. STAGE 0: in = x, writes g_xn (fp32) + g_xh (fp16 of ORIGINAL x).
// STAGE 1: in = g_x2, writes g_x3h (fp16 of normed value).
// ---------------------------------------------------------------------------
template <int STAGE>
__global__ void __launch_bounds__(256) ln_kernel(const float* __restrict__ xin,
                                                 const float* __restrict__ gamma,
                                                 const float* __restrict__ beta) {
    __shared__ float s_part[8], q_part[8], s_stats[2];
    const int row = blockIdx.x;
    const int tid = threadIdx.x;
    const float* src = (STAGE == 0) ? xin : g_x2;
    const float4 v = reinterpret_cast<const float4*>(src + (size_t)row * Dd)[tid];

    float s = v.x + v.y + v.z + v.w;
    float q = v.x * v.x + v.y * v.y + v.z * v.z + v.w * v.w;
#pragma unroll
    for (int o = 16; o > 0; o >>= 1) {
        s += __shfl_xor_sync(0xffffffffu, s, o);
        q += __shfl_xor_sync(0xffffffffu, q, o);
    }
    const int warp = tid >> 5, lane = tid & 31;
    if (lane == 0) { s_part[warp] = s; q_part[warp] = q; }
    __syncthreads();
    if (warp == 0) {
        float ss = (lane < 8) ? s_part[lane] : 0.0f;
        float qq = (lane < 8) ? q_part[lane] : 0.0f;
#pragma unroll
        for (int o = 4; o > 0; o >>= 1) {
            ss += __shfl_xor_sync(0xffffffffu, ss, o);
            qq += __shfl_xor_sync(0xffffffffu, qq, o);
        }
        if (lane == 0) {
            float m = ss * (1.0f / Dd);
            float var = qq * (1.0f / Dd) - m * m;
            s_stats[0] = m;
            s_stats[1] = rsqrtf(var + EPSF);
        }
    }
    __syncthreads();
    const float m = s_stats[0], r = s_stats[1];

    const float4 gg = reinterpret_cast<const float4*>(gamma)[tid];
    const float4 bb = reinterpret_cast<const float4*>(beta)[tid];
    float4 n;
    n.x = (v.x - m) * r * gg.x + bb.x;
    n.y = (v.y - m) * r * gg.y + bb.y;
    n.z = (v.z - m) * r * gg.z + bb.z;
    n.w = (v.w - m) * r * gg.w + bb.w;

    const size_t base = (size_t)row * Dd + (size_t)tid * 4;
    if (STAGE == 0) {
        *reinterpret_cast<float4*>(&g_xn[base]) = n;
        toh4(v, &g_xh[base]);           // fp16 of ORIGINAL x
    } else {
        toh4(n, &g_x3h[base]);          // fp16 of normed x3
    }
}

// ---------------------------------------------------------------------------
// Spiral conv = single-pole complex IIR, 3-phase chunked scan
// ---------------------------------------------------------------------------
template <bool WRITE>
__global__ void __launch_bounds__(256) conv_chunk_kernel(const float* __restrict__ ph_re,
                                                         const float* __restrict__ ph_im,
                                                         const float* __restrict__ phi_re,
                                                         const float* __restrict__ phi_im) {
    const int d = blockIdx.x * blockDim.x + threadIdx.x;
    const int c = blockIdx.y;
    const int b = blockIdx.z;
    const float pr = ph_re[d], pi = ph_im[d];
    const float a = sqrtf(pr * pr + pi * pi);
    const float sc = expf(-a) / a;
    const float zr = pr * sc, zi = pi * sc;
    const float fr = phi_re[d], fi = phi_im[d];

    float Wr, Wi;
    if (WRITE) {
        const float2 w = g_win[(b * NC + c) * Dd + d];
        Wr = w.x; Wi = w.y;
    } else { Wr = 0.0f; Wi = 0.0f; }
    const size_t base = ((size_t)(b * Ll + c * CH)) * Dd + d;
#pragma unroll 4
    for (int j = 0; j < CH; j++) {
        const float xv = g_xn[base + (size_t)j * Dd];
        const float nr = fmaf(zr, Wr, fmaf(-zi, Wi, fr * xv));
        const float ni = fmaf(zr, Wi, fmaf(zi, Wr, fi * xv));
        Wr = nr; Wi = ni;
        if (WRITE) g_conv[base + (size_t)j * Dd] = Wr;
    }
    if (!WRITE) g_carry[(b * NC + c) * Dd + d] = make_float2(Wr, Wi);
}

__global__ void __launch_bounds__(256) conv_scan_kernel(const float* __restrict__ ph_re,
                                                        const float* __restrict__ ph_im,
                                                        const float* __restrict__ lci_re,
                                                        const float* __restrict__ lci_im) {
    const int idx = blockIdx.x * blockDim.x + threadIdx.x;
    const int b = idx >> 10;
    const int d = idx & 1023;
    const float pr = ph_re[d], pi = ph_im[d];
    const float a = sqrtf(pr * pr + pi * pi);
    const float sc = expf(-a) / a;
    float cr = pr * sc, ci = pi * sc;
#pragma unroll
    for (int i = 0; i < 6; i++) {        // phz^64 by squaring
        const float nr = cr * cr - ci * ci;
        const float ni = 2.0f * cr * ci;
        cr = nr; ci = ni;
    }
    float2 car[NC];
#pragma unroll
    for (int c = 0; c < NC; c++) car[c] = g_carry[(b * NC + c) * Dd + d];
    float Wr = lci_re[d], Wi = lci_im[d];
#pragma unroll
    for (int c = 0; c < NC; c++) {
        g_win[(b * NC + c) * Dd + d] = make_float2(Wr, Wi);
        const float nr = cr * Wr - ci * Wi + car[c].x;
        const float ni = cr * Wi + ci * Wr + car[c].y;
        Wr = nr; Wi = ni;
    }
}

// ---------------------------------------------------------------------------
// fp16 single-pass GEMM on mma.sync.  Tile 128x256x64, 8 warps of 64x64,
// 3-stage cp.async ring, XOR-swizzled smem (16B chunk ^ (row&7)).
// A: [M,K] fp16 row-major.  B: [K,N] fp16 row-major (ldmatrix.trans).
// EPI 0: x2 = conv*silu(acc+fc_b)+x   EPI 1: u = fp16(silu(acc+b1))
// EPI 2: out = acc + b2 + x2
// ---------------------------------------------------------------------------
constexpr int BM = 128, BN = 256, BK = 64;
constexpr int NSTAGE = 3;
constexpr int A_BYTES = BM * 128;                  // rows of 64 halfs = 128 B
constexpr int B_BYTES = BK * 512;                  // rows of 256 halfs = 512 B
constexpr int STAGE_BYTES = A_BYTES + B_BYTES;     // 49152
constexpr int GEMM_SMEM_BYTES = NSTAGE * STAGE_BYTES;  // 147456

template <int EPI, int N, int K>
__global__ void __launch_bounds__(256, 1) gemm_kernel(const float* __restrict__ bias,
                                                      const float* __restrict__ extra,
                                                      float* __restrict__ outp) {
    extern __shared__ char dsmem[];

    const __half *Aop, *Bop;
    if constexpr (EPI == 0)      { Aop = g_xh;  Bop = g_fcw; }
    else if constexpr (EPI == 1) { Aop = g_x3h; Bop = g_w1; }
    else                         { Aop = g_u;   Bop = g_w2; }

    const int tid  = threadIdx.x;
    const int lane = tid & 31, warp = tid >> 5;
    const int wm = warp & 1, wn = warp >> 1;      // 2 x 4 warps, each 64x64
    const int bn0 = blockIdx.x * BN;
    const int bm0 = blockIdx.y * BM;
    constexpr int NT = K / BK;
    const uint32_t smem_base = smem_u32(dsmem);

    auto load_tile = [&](int stage, int kb) {
        const uint32_t sA = smem_base + stage * STAGE_BYTES;
        const uint32_t sB = sA + A_BYTES;
        // A: 128 rows x 8 chunks(16B)
#pragma unroll
        for (int i = 0; i < 4; i++) {
            const int q = tid + i * 256;
            const int row = q >> 3, ch = q & 7;
            cp16(sA + row * 128 + ((ch ^ (row & 7)) << 4),
                 Aop + (size_t)(bm0 + row) * K + kb + ch * 8);
        }
        // B: 64 rows x 32 chunks(16B)
#pragma unroll
        for (int i = 0; i < 8; i++) {
            const int q = tid + i * 256;
            const int row = q >> 5, ch = q & 31;
            cp16(sB + row * 512 + ((ch ^ (row & 7)) << 4),
                 Bop + (size_t)(kb + row) * N + bn0 + ch * 8);
        }
        cp_commit();
    };

    float acc[4][8][4];
#pragma unroll
    for (int mi = 0; mi < 4; mi++)
#pragma unroll
        for (int ni = 0; ni < 8; ni++)
#pragma unroll
            for (int e = 0; e < 4; e++) acc[mi][ni][e] = 0.0f;

    load_tile(0, 0);
    load_tile(1, BK);

    for (int kt = 0; kt < NT; kt++) {
        cp_wait<NSTAGE - 2>();          // tile kt resident
        __syncthreads();                // everyone done reading stage (kt-1)%3
        if (kt + NSTAGE - 1 < NT) load_tile((kt + NSTAGE - 1) % NSTAGE,
                                            (kt + NSTAGE - 1) * BK);
        const uint32_t sA = smem_base + (kt % NSTAGE) * STAGE_BYTES;
        const uint32_t sB = sA + A_BYTES;

#pragma unroll
        for (int ks = 0; ks < BK / 16; ks++) {
            uint32_t a[4][4], b[8][2];
#pragma unroll
            for (int mi = 0; mi < 4; mi++) {
                const int row = wm * 64 + mi * 16 + (lane & 15);
                const int ch = ks * 2 + (lane >> 4);
                ldm_x4(a[mi], sA + row * 128 + ((ch ^ (row & 7)) << 4));
            }
#pragma unroll
            for (int ni = 0; ni < 8; ni++) {
                const int row = ks * 16 + (lane & 15);
                const int ch = wn * 8 + ni;
                ldm_x2t(b[ni], sB + row * 512 + ((ch ^ (row & 7)) << 4));
            }
#pragma unroll
            for (int mi = 0; mi < 4; mi++)
#pragma unroll
                for (int ni = 0; ni < 8; ni++)
                    mma_f16(acc[mi][ni], a[mi], b[ni]);
        }
    }

    // ---- fused epilogue ----
#pragma unroll
    for (int mi = 0; mi < 4; mi++) {
#pragma unroll
        for (int ni = 0; ni < 8; ni++) {
            const int col = bn0 + wn * 64 + ni * 8 + (lane & 3) * 2;
            const float b0 = bias[col], b1 = bias[col + 1];
#pragma unroll
            for (int h = 0; h < 2; h++) {
                const int row = bm0 + wm * 64 + mi * 16 + (lane >> 2) + h * 8;
                const size_t idx = (size_t)row * N + col;
                const float v0 = acc[mi][ni][h * 2 + 0] + b0;
                const float v1 = acc[mi][ni][h * 2 + 1] + b1;
                if constexpr (EPI == 0) {
                    const float2 cv = *reinterpret_cast<const float2*>(&g_conv[idx]);
                    const float2 xv = *reinterpret_cast<const float2*>(&extra[idx]);
                    float2 o;
                    o.x = cv.x * silu(v0) + xv.x;
                    o.y = cv.y * silu(v1) + xv.y;
                    *reinterpret_cast<float2*>(&g_x2[idx]) = o;
                } else if constexpr (EPI == 1) {
                    *reinterpret_cast<__half2*>(&g_u[idx]) =
                        __floats2half2_rn(silu(v0), silu(v1));
                } else {
                    const float2 xv = *reinterpret_cast<const float2*>(&g_x2[idx]);
                    float2 o;
                    o.x = v0 + xv.x;
                    o.y = v1 + xv.y;
                    *reinterpret_cast<float2*>(&outp[idx]) = o;
                }
            }
        }
    }
}

// ---------------------------------------------------------------------------
// Launch
// ---------------------------------------------------------------------------
extern "C" void kernel_launch(void* const* d_in, const int* in_sizes, int n_in,
                              void* d_out, int out_size) {
    (void)in_sizes; (void)n_in; (void)out_size;
    const float* x      = (const float*)d_in[0];
    const float* ln_g   = (const float*)d_in[1];
    const float* ln_b   = (const float*)d_in[2];
    const float* fc_w   = (const float*)d_in[3];
    const float* fc_b   = (const float*)d_in[4];
    const float* w1     = (const float*)d_in[5];
    const float* b1     = (const float*)d_in[6];
    const float* w2     = (const float*)d_in[7];
    const float* b2     = (const float*)d_in[8];
    const float* ph_re  = (const float*)d_in[9];
    const float* ph_im  = (const float*)d_in[10];
    const float* phi_re = (const float*)d_in[11];
    const float* phi_im = (const float*)d_in[12];
    const float* lci_re = (const float*)d_in[13];
    const float* lci_im = (const float*)d_in[14];
    float* out = (float*)d_out;

    cudaFuncSetAttribute(gemm_kernel<0, Dd, Dd>,
                         cudaFuncAttributeMaxDynamicSharedMemorySize, GEMM_SMEM_BYTES);
    cudaFuncSetAttribute(gemm_kernel<1, FFd, Dd>,
                         cudaFuncAttributeMaxDynamicSharedMemorySize, GEMM_SMEM_BYTES);
    cudaFuncSetAttribute(gemm_kernel<2, Dd, FFd>,
                         cudaFuncAttributeMaxDynamicSharedMemorySize, GEMM_SMEM_BYTES);

    // 1) weights -> fp16
    wconv_kernel<<<(Dd * FFd + 255) / 256, 256>>>(fc_w, w1, w2);

    // 2) LN1: g_xn = LN(x), g_xh = fp16(x)
    ln_kernel<0><<<ROWS, 256>>>(x, ln_g, ln_b);

    // 3) spiral conv (chunk-local scan -> carry scan -> replay)
    conv_chunk_kernel<false><<<dim3(Dd / 256, NC, Bb), 256>>>(ph_re, ph_im, phi_re, phi_im);
    conv_scan_kernel<<<(Bb * Dd) / 256, 256>>>(ph_re, ph_im, lci_re, lci_im);
    conv_chunk_kernel<true><<<dim3(Dd / 256, NC, Bb), 256>>>(ph_re, ph_im, phi_re, phi_im);

    // 4) fc GEMM + gate/residual: x2 = conv*silu(x@fc_w+fc_b) + x
    gemm_kernel<0, Dd, Dd><<<dim3(Dd / BN, ROWS / BM), 256, GEMM_SMEM_BYTES>>>(fc_b, x, nullptr);

    // 5) LN2: g_x3h = fp16(LN(x2))
    ln_kernel<1><<<ROWS, 256>>>(nullptr, ln_g, ln_b);

    // 6) u = fp16(silu(x3@w1 + b1))
    gemm_kernel<1, FFd, Dd><<<dim3(FFd / BN, ROWS / BM), 256, GEMM_SMEM_BYTES>>>(b1, nullptr, nullptr);

    // 7) out = x2 + u@w2 + b2
    gemm_kernel<2, Dd, FFd><<<dim3(Dd / BN, ROWS / BM), 256, GEMM_SMEM_BYTES>>>(b2, nullptr, out);
}

// round 7
// speedup vs baseline: 2.5405x; 1.3329x over previous
#include <cuda_runtime.h>
#include <cuda_fp16.h>
#include <cstdint>
#include <cstddef>

#define DEV __device__ __forceinline__

// ---------------------------------------------------------------------------
// Problem constants
// ---------------------------------------------------------------------------
constexpr int Bb  = 4;
constexpr int Ll  = 4096;
constexpr int Dd  = 1024;
constexpr int FFd = 2048;
constexpr int ROWS = Bb * Ll;                       // 16384
constexpr size_t BLD = (size_t)ROWS * Dd;
constexpr size_t BLF = (size_t)ROWS * FFd;
constexpr int CH = 64;
constexpr int NC = Ll / CH;                         // 64
constexpr float EPSF = 1e-5f;

// ---------------------------------------------------------------------------
// Scratch (device globals)
// ---------------------------------------------------------------------------
__device__ float   g_xn[BLD];          // LN1 output (conv input, fp32)
__device__ __half  g_xh[BLD];          // fp16 of original x   (A of fc GEMM)
__device__ float   g_conv[BLD];        // conv output
__device__ float   g_x2[BLD];          // conv*y + x
__device__ __half  g_x3h[BLD];         // fp16 of LN2 output   (A of w1 GEMM)
__device__ __half  g_u[BLF];           // fp16 silu(x3@w1+b1)  (A of w2 GEMM)
__device__ float2  g_carry[Bb * NC * Dd];
__device__ float2  g_win[Bb * NC * Dd];
__device__ __half  g_fcw[Dd * Dd];     // fp16 weights, original [K,N] layout
__device__ __half  g_w1[Dd * FFd];
__device__ __half  g_w2[FFd * Dd];

// ---------------------------------------------------------------------------
// PTX helpers (sm_80-level only: cp.async, ldmatrix, mma.sync)
// ---------------------------------------------------------------------------
DEV uint32_t smem_u32(const void* p) { return (uint32_t)__cvta_generic_to_shared(p); }

DEV void cp16(uint32_t s, const void* g) {
    asm volatile("cp.async.cg.shared.global [%0], [%1], 16;\n" :: "r"(s), "l"(g));
}
DEV void cp_commit() { asm volatile("cp.async.commit_group;\n"); }
template <int NN> DEV void cp_wait() { asm volatile("cp.async.wait_group %0;\n" :: "n"(NN)); }

DEV void ldm_x4(uint32_t* r, uint32_t addr) {
    asm volatile("ldmatrix.sync.aligned.m8n8.x4.shared.b16 {%0,%1,%2,%3}, [%4];"
                 : "=r"(r[0]), "=r"(r[1]), "=r"(r[2]), "=r"(r[3]) : "r"(addr));
}
DEV void ldm_x2t(uint32_t* r, uint32_t addr) {
    asm volatile("ldmatrix.sync.aligned.m8n8.x2.trans.shared.b16 {%0,%1}, [%2];"
                 : "=r"(r[0]), "=r"(r[1]) : "r"(addr));
}
DEV void mma_f16(float* c, const uint32_t* a, const uint32_t* b) {
    asm volatile(
        "mma.sync.aligned.m16n8k16.row.col.f32.f16.f16.f32 "
        "{%0,%1,%2,%3}, {%4,%5,%6,%7}, {%8,%9}, {%0,%1,%2,%3};"
        : "+f"(c[0]), "+f"(c[1]), "+f"(c[2]), "+f"(c[3])
        : "r"(a[0]), "r"(a[1]), "r"(a[2]), "r"(a[3]), "r"(b[0]), "r"(b[1]));
}

DEV float silu(float v) { return v / (1.0f + expf(-v)); }

DEV void toh4(float4 v, __half* dst) {
    *reinterpret_cast<__half2*>(dst)     = __floats2half2_rn(v.x, v.y);
    *reinterpret_cast<__half2*>(dst + 2) = __floats2half2_rn(v.z, v.w);
}

// ---------------------------------------------------------------------------
// Weight convert: fp32 -> fp16 (original [K,N] layout kept)
// ---------------------------------------------------------------------------
__global__ void wconv_kernel(const float* __restrict__ fcw,
                             const float* __restrict__ w1,
                             const float* __restrict__ w2) {
    int i = blockIdx.x * blockDim.x + threadIdx.x;
    if (i < Dd * Dd)  g_fcw[i] = __float2half_rn(fcw[i]);
    if (i < Dd * FFd) g_w1[i]  = __float2half_rn(w1[i]);
    if (i < FFd * Dd) g_w2[i]  = __float2half_rn(w2[i]);
}

// ---------------------------------------------------------------------------
// LayerNorm. STAGE 0: in = x, writes g_xn (fp32) + g_xh (fp16 of ORIGINAL x).
// STAGE 1: in = g_x2, writes g_x3h (fp16 of normed value).
// ---------------------------------------------------------------------------
template <int STAGE>
__global__ void __launch_bounds__(256) ln_kernel(const float* __restrict__ xin,
                                                 const float* __restrict__ gamma,
                                                 const float* __restrict__ beta) {
    __shared__ float s_part[8], q_part[8], s_stats[2];
    const int row = blockIdx.x;
    const int tid = threadIdx.x;
    const float* src = (STAGE == 0) ? xin : g_x2;
    const float4 v = reinterpret_cast<const float4*>(src + (size_t)row * Dd)[tid];

    float s = v.x + v.y + v.z + v.w;
    float q = v.x * v.x + v.y * v.y + v.z * v.z + v.w * v.w;
#pragma unroll
    for (int o = 16; o > 0; o >>= 1) {
        s += __shfl_xor_sync(0xffffffffu, s, o);
        q += __shfl_xor_sync(0xffffffffu, q, o);
    }
    const int warp = tid >> 5, lane = tid & 31;
    if (lane == 0) { s_part[warp] = s; q_part[warp] = q; }
    __syncthreads();
    if (warp == 0) {
        float ss = (lane < 8) ? s_part[lane] : 0.0f;
        float qq = (lane < 8) ? q_part[lane] : 0.0f;
#pragma unroll
        for (int o = 4; o > 0; o >>= 1) {
            ss += __shfl_xor_sync(0xffffffffu, ss, o);
            qq += __shfl_xor_sync(0xffffffffu, qq, o);
        }
        if (lane == 0) {
            float m = ss * (1.0f / Dd);
            float var = qq * (1.0f / Dd) - m * m;
            s_stats[0] = m;
            s_stats[1] = rsqrtf(var + EPSF);
        }
    }
    __syncthreads();
    const float m = s_stats[0], r = s_stats[1];

    const float4 gg = reinterpret_cast<const float4*>(gamma)[tid];
    const float4 bb = reinterpret_cast<const float4*>(beta)[tid];
    float4 n;
    n.x = (v.x - m) * r * gg.x + bb.x;
    n.y = (v.y - m) * r * gg.y + bb.y;
    n.z = (v.z - m) * r * gg.z + bb.z;
    n.w = (v.w - m) * r * gg.w + bb.w;

    const size_t base = (size_t)row * Dd + (size_t)tid * 4;
    if (STAGE == 0) {
        *reinterpret_cast<float4*>(&g_xn[base]) = n;
        toh4(v, &g_xh[base]);           // fp16 of ORIGINAL x
    } else {
        toh4(n, &g_x3h[base]);          // fp16 of normed x3
    }
}

// ---------------------------------------------------------------------------
// Spiral conv = single-pole complex IIR, 3-phase chunked scan
// ---------------------------------------------------------------------------
template <bool WRITE>
__global__ void __launch_bounds__(256) conv_chunk_kernel(const float* __restrict__ ph_re,
                                                         const float* __restrict__ ph_im,
                                                         const float* __restrict__ phi_re,
                                                         const float* __restrict__ phi_im) {
    const int d = blockIdx.x * blockDim.x + threadIdx.x;
    const int c = blockIdx.y;
    const int b = blockIdx.z;
    const float pr = ph_re[d], pi = ph_im[d];
    const float a = sqrtf(pr * pr + pi * pi);
    const float sc = expf(-a) / a;
    const float zr = pr * sc, zi = pi * sc;
    const float fr = phi_re[d], fi = phi_im[d];

    float Wr, Wi;
    if (WRITE) {
        const float2 w = g_win[(b * NC + c) * Dd + d];
        Wr = w.x; Wi = w.y;
    } else { Wr = 0.0f; Wi = 0.0f; }
    const size_t base = ((size_t)(b * Ll + c * CH)) * Dd + d;
#pragma unroll 8
    for (int j = 0; j < CH; j++) {
        const float xv = g_xn[base + (size_t)j * Dd];
        const float nr = fmaf(zr, Wr, fmaf(-zi, Wi, fr * xv));
        const float ni = fmaf(zr, Wi, fmaf(zi, Wr, fi * xv));
        Wr = nr; Wi = ni;
        if (WRITE) g_conv[base + (size_t)j * Dd] = Wr;
    }
    if (!WRITE) g_carry[(b * NC + c) * Dd + d] = make_float2(Wr, Wi);
}

__global__ void __launch_bounds__(256) conv_scan_kernel(const float* __restrict__ ph_re,
                                                        const float* __restrict__ ph_im,
                                                        const float* __restrict__ lci_re,
                                                        const float* __restrict__ lci_im) {
    const int idx = blockIdx.x * blockDim.x + threadIdx.x;
    const int b = idx >> 10;
    const int d = idx & 1023;
    const float pr = ph_re[d], pi = ph_im[d];
    const float a = sqrtf(pr * pr + pi * pi);
    const float sc = expf(-a) / a;
    float cr = pr * sc, ci = pi * sc;
#pragma unroll
    for (int i = 0; i < 6; i++) {        // phz^64 by squaring
        const float nr = cr * cr - ci * ci;
        const float ni = 2.0f * cr * ci;
        cr = nr; ci = ni;
    }
    float2 car[NC];
#pragma unroll
    for (int c = 0; c < NC; c++) car[c] = g_carry[(b * NC + c) * Dd + d];
    float Wr = lci_re[d], Wi = lci_im[d];
#pragma unroll
    for (int c = 0; c < NC; c++) {
        g_win[(b * NC + c) * Dd + d] = make_float2(Wr, Wi);
        const float nr = cr * Wr - ci * Wi + car[c].x;
        const float ni = cr * Wi + ci * Wr + car[c].y;
        Wr = nr; Wi = ni;
    }
}

// ---------------------------------------------------------------------------
// fp16 single-pass GEMM on mma.sync.  Tile 128x128x64, 8 warps of 64x32,
// 3-stage cp.async ring (96KB smem -> 2 CTAs/SM), XOR-swizzled smem.
// A: [M,K] fp16 row-major.  B: [K,N] fp16 row-major (ldmatrix.trans).
// EPI 0: x2 = conv*silu(acc+fc_b)+x   EPI 1: u = fp16(silu(acc+b1))
// EPI 2: out = acc + b2 + x2
// ---------------------------------------------------------------------------
constexpr int BM = 128, BN = 128, BK = 64;
constexpr int NSTAGE = 3;
constexpr int A_BYTES = BM * 128;                  // rows of 64 halfs = 128 B
constexpr int B_BYTES = BK * 256;                  // rows of 128 halfs = 256 B
constexpr int STAGE_BYTES = A_BYTES + B_BYTES;     // 32768
constexpr int GEMM_SMEM_BYTES = NSTAGE * STAGE_BYTES;  // 98304

template <int EPI, int N, int K>
__global__ void __launch_bounds__(256, 2) gemm_kernel(const float* __restrict__ bias,
                                                      const float* __restrict__ extra,
                                                      float* __restrict__ outp) {
    extern __shared__ char dsmem[];

    const __half *Aop, *Bop;
    if constexpr (EPI == 0)      { Aop = g_xh;  Bop = g_fcw; }
    else if constexpr (EPI == 1) { Aop = g_x3h; Bop = g_w1; }
    else                         { Aop = g_u;   Bop = g_w2; }

    const int tid  = threadIdx.x;
    const int lane = tid & 31, warp = tid >> 5;
    const int wm = warp & 1, wn = warp >> 1;      // 2 x 4 warps, each 64x32
    const int bn0 = blockIdx.x * BN;
    const int bm0 = blockIdx.y * BM;
    constexpr int NT = K / BK;
    const uint32_t smem_base = smem_u32(dsmem);

    auto load_tile = [&](int stage, int kb) {
        const uint32_t sA = smem_base + stage * STAGE_BYTES;
        const uint32_t sB = sA + A_BYTES;
        // A: 128 rows x 8 chunks(16B) = 1024 chunks
#pragma unroll
        for (int i = 0; i < 4; i++) {
            const int q = tid + i * 256;
            const int row = q >> 3, ch = q & 7;
            cp16(sA + row * 128 + ((ch ^ (row & 7)) << 4),
                 Aop + (size_t)(bm0 + row) * K + kb + ch * 8);
        }
        // B: 64 rows x 16 chunks(16B) = 1024 chunks
#pragma unroll
        for (int i = 0; i < 4; i++) {
            const int q = tid + i * 256;
            const int row = q >> 4, ch = q & 15;
            cp16(sB + row * 256 + ((ch ^ (row & 7)) << 4),
                 Bop + (size_t)(kb + row) * N + bn0 + ch * 8);
        }
        cp_commit();
    };

    float acc[4][4][4];
#pragma unroll
    for (int mi = 0; mi < 4; mi++)
#pragma unroll
        for (int ni = 0; ni < 4; ni++)
#pragma unroll
            for (int e = 0; e < 4; e++) acc[mi][ni][e] = 0.0f;

    load_tile(0, 0);
    load_tile(1, BK);

    for (int kt = 0; kt < NT; kt++) {
        cp_wait<NSTAGE - 2>();          // tile kt resident
        __syncthreads();                // everyone done reading stage (kt-1)%3
        if (kt + NSTAGE - 1 < NT) load_tile((kt + NSTAGE - 1) % NSTAGE,
                                            (kt + NSTAGE - 1) * BK);
        const uint32_t sA = smem_base + (kt % NSTAGE) * STAGE_BYTES;
        const uint32_t sB = sA + A_BYTES;

#pragma unroll
        for (int ks = 0; ks < BK / 16; ks++) {
            uint32_t a[4][4], b[4][2];
#pragma unroll
            for (int mi = 0; mi < 4; mi++) {
                const int row = wm * 64 + mi * 16 + (lane & 15);
                const int ch = ks * 2 + (lane >> 4);
                ldm_x4(a[mi], sA + row * 128 + ((ch ^ (row & 7)) << 4));
            }
#pragma unroll
            for (int ni = 0; ni < 4; ni++) {
                const int row = ks * 16 + (lane & 15);
                const int ch = wn * 4 + ni;
                ldm_x2t(b[ni], sB + row * 256 + ((ch ^ (row & 7)) << 4));
            }
#pragma unroll
            for (int mi = 0; mi < 4; mi++)
#pragma unroll
                for (int ni = 0; ni < 4; ni++)
                    mma_f16(acc[mi][ni], a[mi], b[ni]);
        }
    }

    // ---- fused epilogue ----
#pragma unroll
    for (int mi = 0; mi < 4; mi++) {
#pragma unroll
        for (int ni = 0; ni < 4; ni++) {
            const int col = bn0 + wn * 32 + ni * 8 + (lane & 3) * 2;
            const float b0 = bias[col], b1 = bias[col + 1];
#pragma unroll
            for (int h = 0; h < 2; h++) {
                const int row = bm0 + wm * 64 + mi * 16 + (lane >> 2) + h * 8;
                const size_t idx = (size_t)row * N + col;
                const float v0 = acc[mi][ni][h * 2 + 0] + b0;
                const float v1 = acc[mi][ni][h * 2 + 1] + b1;
                if constexpr (EPI == 0) {
                    const float2 cv = *reinterpret_cast<const float2*>(&g_conv[idx]);
                    const float2 xv = *reinterpret_cast<const float2*>(&extra[idx]);
                    float2 o;
                    o.x = cv.x * silu(v0) + xv.x;
                    o.y = cv.y * silu(v1) + xv.y;
                    *reinterpret_cast<float2*>(&g_x2[idx]) = o;
                } else if constexpr (EPI == 1) {
                    *reinterpret_cast<__half2*>(&g_u[idx]) =
                        __floats2half2_rn(silu(v0), silu(v1));
                } else {
                    const float2 xv = *reinterpret_cast<const float2*>(&g_x2[idx]);
                    float2 o;
                    o.x = v0 + xv.x;
                    o.y = v1 + xv.y;
                    *reinterpret_cast<float2*>(&outp[idx]) = o;
                }
            }
        }
    }
}

// ---------------------------------------------------------------------------
// Launch
// ---------------------------------------------------------------------------
extern "C" void kernel_launch(void* const* d_in, const int* in_sizes, int n_in,
                              void* d_out, int out_size) {
    (void)in_sizes; (void)n_in; (void)out_size;
    const float* x      = (const float*)d_in[0];
    const float* ln_g   = (const float*)d_in[1];
    const float* ln_b   = (const float*)d_in[2];
    const float* fc_w   = (const float*)d_in[3];
    const float* fc_b   = (const float*)d_in[4];
    const float* w1     = (const float*)d_in[5];
    const float* b1     = (const float*)d_in[6];
    const float* w2     = (const float*)d_in[7];
    const float* b2     = (const float*)d_in[8];
    const float* ph_re  = (const float*)d_in[9];
    const float* ph_im  = (const float*)d_in[10];
    const float* phi_re = (const float*)d_in[11];
    const float* phi_im = (const float*)d_in[12];
    const float* lci_re = (const float*)d_in[13];
    const float* lci_im = (const float*)d_in[14];
    float* out = (float*)d_out;

    cudaFuncSetAttribute(gemm_kernel<0, Dd, Dd>,
                         cudaFuncAttributeMaxDynamicSharedMemorySize, GEMM_SMEM_BYTES);
    cudaFuncSetAttribute(gemm_kernel<1, FFd, Dd>,
                         cudaFuncAttributeMaxDynamicSharedMemorySize, GEMM_SMEM_BYTES);
    cudaFuncSetAttribute(gemm_kernel<2, Dd, FFd>,
                         cudaFuncAttributeMaxDynamicSharedMemorySize, GEMM_SMEM_BYTES);

    // 1) weights -> fp16
    wconv_kernel<<<(Dd * FFd + 255) / 256, 256>>>(fc_w, w1, w2);

    // 2) LN1: g_xn = LN(x), g_xh = fp16(x)
    ln_kernel<0><<<ROWS, 256>>>(x, ln_g, ln_b);

    // 3) spiral conv (chunk-local scan -> carry scan -> replay)
    conv_chunk_kernel<false><<<dim3(Dd / 256, NC, Bb), 256>>>(ph_re, ph_im, phi_re, phi_im);
    conv_scan_kernel<<<(Bb * Dd) / 256, 256>>>(ph_re, ph_im, lci_re, lci_im);
    conv_chunk_kernel<true><<<dim3(Dd / 256, NC, Bb), 256>>>(ph_re, ph_im, phi_re, phi_im);

    // 4) fc GEMM + gate/residual: x2 = conv*silu(x@fc_w+fc_b) + x
    gemm_kernel<0, Dd, Dd><<<dim3(Dd / BN, ROWS / BM), 256, GEMM_SMEM_BYTES>>>(fc_b, x, nullptr);

    // 5) LN2: g_x3h = fp16(LN(x2))
    ln_kernel<1><<<ROWS, 256>>>(nullptr, ln_g, ln_b);

    // 6) u = fp16(silu(x3@w1 + b1))
    gemm_kernel<1, FFd, Dd><<<dim3(FFd / BN, ROWS / BM), 256, GEMM_SMEM_BYTES>>>(b1, nullptr, nullptr);

    // 7) out = x2 + u@w2 + b2
    gemm_kernel<2, Dd, FFd><<<dim3(Dd / BN, ROWS / BM), 256, GEMM_SMEM_BYTES>>>(b2, nullptr, out);
}